// round 1
// baseline (speedup 1.0000x reference)
#include <cuda_runtime.h>

#define B_ 8
#define H_ 352
#define W_ 1216
#define PLANE (H_*W_)
#define NPIX (B_*PLANE)
#define MAXR 32

// Per-direction precomputed tables:
//   .x = g   = exp(-min(var_c, 5)) * mask      (confidence weight; 0 iff mask==0)
//   .y = e   = exp(+/- plog)                   (per-step log-gradient factor)
//   .z = g*d = g * depthin                     (weighted depth hypothesis)
__device__ float4 g_dir0[NPIX]; // +w  (sources at w-n), uses var[0], exp(+plog_h)
__device__ float4 g_dir1[NPIX]; // -w  (sources at w+n), uses var[1], exp(-plog_h)
__device__ float4 g_dir2[NPIX]; // +h  (sources at h-n), uses var[2], exp(+plog_v)
__device__ float4 g_dir3[NPIX]; // -h  (sources at h+n), uses var[3], exp(-plog_v)

__global__ void prep_kernel(const float* __restrict__ pred_log,
                            const int*   __restrict__ mask,
                            const float* __restrict__ variance,
                            const float* __restrict__ depthin)
{
    int idx = blockIdx.x * blockDim.x + threadIdx.x;
    if (idx >= NPIX) return;
    int b = idx / PLANE;
    int p = idx - b * PLANE;

    const float* pl = pred_log + (size_t)b * 2 * PLANE + p;
    float ph = pl[0];
    float pv = pl[PLANE];

    float m = (mask[idx] != 0) ? 1.0f : 0.0f;

    const float* vv = variance + (size_t)b * 4 * PLANE + p;
    float v0 = vv[0];
    float v1 = vv[PLANE];
    float v2 = vv[2 * PLANE];
    float v3 = vv[3 * PLANE];

    float d = depthin[idx];

    float eph = expf(ph),  rph = expf(-ph);
    float epv = expf(pv),  rpv = expf(-pv);
    float g0 = expf(-fminf(v0, 5.0f)) * m;
    float g1 = expf(-fminf(v1, 5.0f)) * m;
    float g2 = expf(-fminf(v2, 5.0f)) * m;
    float g3 = expf(-fminf(v3, 5.0f)) * m;

    g_dir0[idx] = make_float4(g0, eph, g0 * d, 0.0f);
    g_dir1[idx] = make_float4(g1, rph, g1 * d, 0.0f);
    g_dir2[idx] = make_float4(g2, epv, g2 * d, 0.0f);
    g_dir3[idx] = make_float4(g3, rpv, g3 * d, 0.0f);
}

__global__ void crf_kernel(const int*   __restrict__ mask,
                           const float* __restrict__ depthin,
                           const float* __restrict__ lam_p,
                           float*       __restrict__ out)
{
    int w = blockIdx.x * blockDim.x + threadIdx.x;
    if (w >= W_) return;
    int h = blockIdx.y;
    int b = blockIdx.z;
    int idx = (b * H_ + h) * W_ + w;

    float din = depthin[idx];
    if (mask[idx] == 0) { out[idx] = din; return; }

    float aw = 0.0f, awd = 0.0f;

    // +w direction: sources at w-n; log-factor product INCLUDES the source pixel.
    {
        float prod = 1.0f;
        int lim = min(MAXR, w);
        #pragma unroll 4
        for (int n = 1; n <= lim; ++n) {
            float4 t = g_dir0[idx - n];
            prod *= t.y;
            aw  += t.x;
            awd += t.z * prod;
            if (t.x == 0.0f) break;  // mask broke the path
        }
    }
    // -w direction: sources at w+n; product covers positions w .. w+n-1 (excludes source).
    {
        float prod = g_dir1[idx].y;  // exp(-plog_h[w]) : the j=0 term
        int lim = min(MAXR, W_ - 1 - w);
        #pragma unroll 4
        for (int n = 1; n <= lim; ++n) {
            float4 t = g_dir1[idx + n];
            aw  += t.x;
            awd += t.z * prod;
            if (t.x == 0.0f) break;
            prod *= t.y;
        }
    }
    // +h direction: sources at h-n.
    {
        float prod = 1.0f;
        int lim = min(MAXR, h);
        #pragma unroll 4
        for (int n = 1; n <= lim; ++n) {
            float4 t = g_dir2[idx - n * W_];
            prod *= t.y;
            aw  += t.x;
            awd += t.z * prod;
            if (t.x == 0.0f) break;
        }
    }
    // -h direction: sources at h+n.
    {
        float prod = g_dir3[idx].y;  // exp(-plog_v[h]) : the j=0 term
        int lim = min(MAXR, H_ - 1 - h);
        #pragma unroll 4
        for (int n = 1; n <= lim; ++n) {
            float4 t = g_dir3[idx + n * W_];
            aw  += t.x;
            awd += t.z * prod;
            if (t.x == 0.0f) break;
            prod *= t.y;
        }
    }

    float o = din;
    if (aw > 0.0f) {
        float lat = awd / fmaxf(aw, 1e-12f);
        if (lat > 0.0f) {
            float lam = lam_p[0];
            o = din * (1.0f - lam) + lat * lam;
        }
    }
    out[idx] = o;
}

extern "C" void kernel_launch(void* const* d_in, const int* in_sizes, int n_in,
                              void* d_out, int out_size)
{
    const float* pred_log = (const float*)d_in[0];
    const int*   mask     = (const int*)  d_in[1];
    const float* variance = (const float*)d_in[2];
    const float* depthin  = (const float*)d_in[3];
    const float* lam      = (const float*)d_in[4];
    float* out = (float*)d_out;

    const int threads = 256;
    prep_kernel<<<(NPIX + threads - 1) / threads, threads>>>(pred_log, mask, variance, depthin);

    dim3 grid((W_ + threads - 1) / threads, H_, B_);
    crf_kernel<<<grid, threads>>>(mask, depthin, lam, out);
}